// round 2
// baseline (speedup 1.0000x reference)
#include <cuda_runtime.h>
#include <cuda_fp16.h>
#include <cstdint>

#define BV 8
#define TV 512
#define DV 2048
#define HV 2048
#define STEPS (BV * TV)
#define R4H (4 * HV)
#define GRID 148
#define JPC 14
#define ROWS (4 * JPC)
#define NTH 256
#define LSTM_SMEM (ROWS * HV * 2 + 2 * ROWS * 4)
#define OUTSTRIDE ((size_t)STEPS * HV)

__device__ float g_xp[(size_t)STEPS * R4H];
__device__ __align__(16) float g_h[2][HV];
__device__ unsigned int g_bar;

// ---------------------------------------------------------------- init
__global__ void init_kernel(const float* __restrict__ h0) {
    int i = blockIdx.x * blockDim.x + threadIdx.x;
    if (i == 0) g_bar = 0u;
    if (i < HV) g_h[0][i] = h0[i];
}

// ---------------------------------------------------------------- GEMM
#define GBK 16
#define GPAD 132
__global__ void __launch_bounds__(256, 2)
gemm_xp(const float* __restrict__ A, const float* __restrict__ Bm,
        const float* __restrict__ bias) {
    __shared__ __align__(16) float Xs[2][GBK][GPAD];
    __shared__ __align__(16) float Ws2[2][GBK][GPAD];
    const int tid = threadIdx.x;
    const int m0 = blockIdx.x * 128, n0 = blockIdx.y * 128;
    const int tx = (tid & 15) << 3, ty = (tid >> 4) << 3;
    const int ln = tid >> 1, lk = (tid & 1) << 3;

    const float* Ald = A + (size_t)(n0 + ln) * DV + lk;
    const float* Bld = Bm + (size_t)(m0 + ln) * DV + lk;
    float4 ax = *(const float4*)(Ald), ay = *(const float4*)(Ald + 4);
    float4 bx = *(const float4*)(Bld), by = *(const float4*)(Bld + 4);

    float acc[8][8];
#pragma unroll
    for (int i = 0; i < 8; ++i)
#pragma unroll
        for (int j = 0; j < 8; ++j) acc[i][j] = 0.f;

    int buf = 0;
#pragma unroll
    for (int m = 0; m < 4; ++m) {
        Xs[0][lk + m][ln] = (&ax.x)[m];   Xs[0][lk + 4 + m][ln] = (&ay.x)[m];
        Ws2[0][lk + m][ln] = (&bx.x)[m];  Ws2[0][lk + 4 + m][ln] = (&by.x)[m];
    }
    __syncthreads();

    const int NKT = DV / GBK;
    for (int kt = 0; kt < NKT; ++kt) {
        if (kt + 1 < NKT) {
            const float* An = Ald + (kt + 1) * GBK;
            const float* Bn = Bld + (kt + 1) * GBK;
            ax = *(const float4*)(An); ay = *(const float4*)(An + 4);
            bx = *(const float4*)(Bn); by = *(const float4*)(Bn + 4);
        }
#pragma unroll
        for (int kk = 0; kk < GBK; ++kk) {
            float av[8], bv[8];
            *(float4*)&av[0] = *(const float4*)&Xs[buf][kk][ty];
            *(float4*)&av[4] = *(const float4*)&Xs[buf][kk][ty + 4];
            *(float4*)&bv[0] = *(const float4*)&Ws2[buf][kk][tx];
            *(float4*)&bv[4] = *(const float4*)&Ws2[buf][kk][tx + 4];
#pragma unroll
            for (int i = 0; i < 8; ++i)
#pragma unroll
                for (int j = 0; j < 8; ++j)
                    acc[i][j] = fmaf(av[i], bv[j], acc[i][j]);
        }
        if (kt + 1 < NKT) {
            buf ^= 1;
            __syncthreads();
#pragma unroll
            for (int m = 0; m < 4; ++m) {
                Xs[buf][lk + m][ln] = (&ax.x)[m];   Xs[buf][lk + 4 + m][ln] = (&ay.x)[m];
                Ws2[buf][lk + m][ln] = (&bx.x)[m];  Ws2[buf][lk + 4 + m][ln] = (&by.x)[m];
            }
            __syncthreads();
        }
    }
    float4 bb0 = *(const float4*)(bias + m0 + tx);
    float4 bb1 = *(const float4*)(bias + m0 + tx + 4);
#pragma unroll
    for (int i = 0; i < 8; ++i) {
        float* cp = g_xp + (size_t)(n0 + ty + i) * R4H + m0 + tx;
        float4 o0, o1;
#pragma unroll
        for (int j = 0; j < 4; ++j) { (&o0.x)[j] = acc[i][j] + (&bb0.x)[j];
                                      (&o1.x)[j] = acc[i][4 + j] + (&bb1.x)[j]; }
        *(float4*)cp = o0; *(float4*)(cp + 4) = o1;
    }
}

// ---------------------------------------------------------------- LSTM
__global__ void __launch_bounds__(NTH, 1)
lstm_kernel(const float* __restrict__ c0, const float* __restrict__ W_hh,
            const float* __restrict__ b_hh, float* __restrict__ out) {
    extern __shared__ __align__(16) unsigned char smem_raw[];
    __half* Ws = reinterpret_cast<__half*>(smem_raw);
    float* pre_part = reinterpret_cast<float*>(smem_raw + (size_t)ROWS * HV * 2);

    const int tid = threadIdx.x, cta = blockIdx.x;
    const int j0 = cta * JPC;
    int J = HV - j0; if (J > JPC) J = JPC; if (J < 0) J = 0;

    // stage W_hh slice -> SMEM fp16. row rl = jl*4+gate <- W_hh[gate*HV + j0+jl]
    for (int e = tid; e < ROWS * HV; e += NTH) {
        int rl = e >> 11, k = e & (HV - 1);
        int jl = rl >> 2, gate = rl & 3;
        float w = (jl < J) ? W_hh[((size_t)gate * HV + (size_t)(j0 + jl)) * HV + k] : 0.f;
        Ws[e] = __float2half(w);
    }

    const int warp = tid >> 5, lane = tid & 31;
    const int grp = warp >> 1, hf = warp & 1;
    const int kb = hf << 10;
    const int rbase = grp * JPC;

    float c_val = 0.f, b_r[4];
#pragma unroll
    for (int g = 0; g < 4; ++g) b_r[g] = 0.f;
    if (tid < J) {
        c_val = c0[j0 + tid];
#pragma unroll
        for (int g = 0; g < 4; ++g) b_r[g] = b_hh[g * HV + j0 + tid];
    }
    __syncthreads();

    const uint4* Wq = reinterpret_cast<const uint4*>(Ws);
    const size_t wbase = (size_t)rbase * 256 + (size_t)hf * 128 + lane;

    for (int t = 0; t < STEPS; ++t) {
        const int p = t & 1;

        float xp_r[4];
        if (tid < J) {
#pragma unroll
            for (int g = 0; g < 4; ++g)
                xp_r[g] = g_xp[(size_t)t * R4H + g * HV + j0 + tid];
        }

        float hreg[32];
        {
            const float* hb = &g_h[p][kb + (lane << 3)];
#pragma unroll
            for (int it = 0; it < 4; ++it) {
                float4 v0 = __ldcg((const float4*)(hb + it * 256));
                float4 v1 = __ldcg((const float4*)(hb + it * 256 + 4));
#pragma unroll
                for (int m = 0; m < 4; ++m) {
                    hreg[it * 8 + m] = (&v0.x)[m];
                    hreg[it * 8 + 4 + m] = (&v1.x)[m];
                }
            }
        }

        float acc[JPC];
#pragma unroll
        for (int r = 0; r < JPC; ++r) acc[r] = 0.f;
#pragma unroll
        for (int it = 0; it < 4; ++it) {
#pragma unroll
            for (int r = 0; r < JPC; ++r) {
                uint4 w = Wq[wbase + (size_t)r * 256 + it * 32];
                float a = acc[r];
                float2 f;
                f = __half22float2(*(const __half2*)&w.x);
                a = fmaf(f.x, hreg[it * 8 + 0], a); a = fmaf(f.y, hreg[it * 8 + 1], a);
                f = __half22float2(*(const __half2*)&w.y);
                a = fmaf(f.x, hreg[it * 8 + 2], a); a = fmaf(f.y, hreg[it * 8 + 3], a);
                f = __half22float2(*(const __half2*)&w.z);
                a = fmaf(f.x, hreg[it * 8 + 4], a); a = fmaf(f.y, hreg[it * 8 + 5], a);
                f = __half22float2(*(const __half2*)&w.w);
                a = fmaf(f.x, hreg[it * 8 + 6], a); a = fmaf(f.y, hreg[it * 8 + 7], a);
                acc[r] = a;
            }
        }
#pragma unroll
        for (int r = 0; r < JPC; ++r) {
            float v = acc[r];
            v += __shfl_xor_sync(~0u, v, 16);
            v += __shfl_xor_sync(~0u, v, 8);
            v += __shfl_xor_sync(~0u, v, 4);
            v += __shfl_xor_sync(~0u, v, 2);
            v += __shfl_xor_sync(~0u, v, 1);
            if (lane == 0) pre_part[hf * ROWS + rbase + r] = v;
        }
        __syncthreads();

        if (tid < J) {
            const int rl = tid << 2;
            float pi = xp_r[0] + b_r[0] + pre_part[rl + 0] + pre_part[ROWS + rl + 0];
            float pf = xp_r[1] + b_r[1] + pre_part[rl + 1] + pre_part[ROWS + rl + 1];
            float po = xp_r[2] + b_r[2] + pre_part[rl + 2] + pre_part[ROWS + rl + 2];
            float pg = xp_r[3] + b_r[3] + pre_part[rl + 3] + pre_part[ROWS + rl + 3];
            float i_t = 1.0f / (1.0f + expf(-pi));
            float f_t = 1.0f / (1.0f + expf(-pf));
            float o_t = 1.0f / (1.0f + expf(-po));
            float g_t = tanhf(pg);
            c_val = c_val * f_t + i_t * g_t;
            float h_n = o_t * tanhf(c_val);
            g_h[p ^ 1][j0 + tid] = h_n;
            size_t oi = (size_t)t * HV + j0 + tid;
            out[oi] = h_n;
            out[OUTSTRIDE + oi] = f_t;
            out[2 * OUTSTRIDE + oi] = i_t;
        }

        // grid barrier
        __syncthreads();
        if (tid == 0) {
            __threadfence();
            atomicAdd(&g_bar, 1u);
            const unsigned tgt = (unsigned)(t + 1) * GRID;
            while (atomicAdd(&g_bar, 0u) < tgt) {}
            __threadfence();
        }
        __syncthreads();
    }
}

extern "C" void kernel_launch(void* const* d_in, const int* in_sizes, int n_in,
                              void* d_out, int out_size) {
    const float* input_ = (const float*)d_in[0];
    const float* h0 = (const float*)d_in[1];
    const float* c0 = (const float*)d_in[2];
    const float* W_ih = (const float*)d_in[3];
    const float* b_ih = (const float*)d_in[4];
    const float* W_hh = (const float*)d_in[5];
    const float* b_hh = (const float*)d_in[6];
    float* out = (float*)d_out;

    static int smem_set = 0;
    if (!smem_set) {
        cudaFuncSetAttribute(lstm_kernel, cudaFuncAttributeMaxDynamicSharedMemorySize,
                             LSTM_SMEM);
        smem_set = 1;
    }

    init_kernel<<<16, 128>>>(h0);
    gemm_xp<<<dim3(R4H / 128, STEPS / 128), 256>>>(input_, W_ih, b_ih);
    lstm_kernel<<<GRID, NTH, LSTM_SMEM>>>(c0, W_hh, b_hh, out);
}

// round 3
// speedup vs baseline: 1.0387x; 1.0387x over previous
#include <cuda_runtime.h>
#include <cuda_fp16.h>
#include <cstdint>

#define BV 8
#define TV 512
#define DV 2048
#define HV 2048
#define STEPS (BV * TV)
#define R4H (4 * HV)
#define GRID 148
#define JPC 14
#define ROWS (4 * JPC)
#define NTH 256
#define LSTM_SMEM (ROWS * HV * 2 + 2 * ROWS * 4)
#define OUTSTRIDE ((size_t)STEPS * HV)

__device__ float g_xp[(size_t)STEPS * R4H];
__device__ __align__(16) float g_h[2][HV];
__device__ unsigned int g_bar;

// ---------------------------------------------------------------- init
__global__ void init_kernel(const float* __restrict__ h0) {
    int i = blockIdx.x * blockDim.x + threadIdx.x;
    if (i == 0) g_bar = 0u;
    if (i < HV) g_h[0][i] = h0[i];
}

// ---------------------------------------------------------------- GEMM
#define GBK 16
#define GPAD 132
__global__ void __launch_bounds__(256, 2)
gemm_xp(const float* __restrict__ A, const float* __restrict__ Bm,
        const float* __restrict__ bias) {
    __shared__ __align__(16) float Xs[2][GBK][GPAD];
    __shared__ __align__(16) float Ws2[2][GBK][GPAD];
    const int tid = threadIdx.x;
    const int m0 = blockIdx.x * 128, n0 = blockIdx.y * 128;
    const int tx = (tid & 15) << 3, ty = (tid >> 4) << 3;
    const int ln = tid >> 1, lk = (tid & 1) << 3;

    const float* Ald = A + (size_t)(n0 + ln) * DV + lk;
    const float* Bld = Bm + (size_t)(m0 + ln) * DV + lk;
    float4 ax = *(const float4*)(Ald), ay = *(const float4*)(Ald + 4);
    float4 bx = *(const float4*)(Bld), by = *(const float4*)(Bld + 4);

    float acc[8][8];
#pragma unroll
    for (int i = 0; i < 8; ++i)
#pragma unroll
        for (int j = 0; j < 8; ++j) acc[i][j] = 0.f;

    int buf = 0;
#pragma unroll
    for (int m = 0; m < 4; ++m) {
        Xs[0][lk + m][ln] = (&ax.x)[m];   Xs[0][lk + 4 + m][ln] = (&ay.x)[m];
        Ws2[0][lk + m][ln] = (&bx.x)[m];  Ws2[0][lk + 4 + m][ln] = (&by.x)[m];
    }
    __syncthreads();

    const int NKT = DV / GBK;
    for (int kt = 0; kt < NKT; ++kt) {
        if (kt + 1 < NKT) {
            const float* An = Ald + (kt + 1) * GBK;
            const float* Bn = Bld + (kt + 1) * GBK;
            ax = *(const float4*)(An); ay = *(const float4*)(An + 4);
            bx = *(const float4*)(Bn); by = *(const float4*)(Bn + 4);
        }
#pragma unroll
        for (int kk = 0; kk < GBK; ++kk) {
            float av[8], bv[8];
            *(float4*)&av[0] = *(const float4*)&Xs[buf][kk][ty];
            *(float4*)&av[4] = *(const float4*)&Xs[buf][kk][ty + 4];
            *(float4*)&bv[0] = *(const float4*)&Ws2[buf][kk][tx];
            *(float4*)&bv[4] = *(const float4*)&Ws2[buf][kk][tx + 4];
#pragma unroll
            for (int i = 0; i < 8; ++i)
#pragma unroll
                for (int j = 0; j < 8; ++j)
                    acc[i][j] = fmaf(av[i], bv[j], acc[i][j]);
        }
        if (kt + 1 < NKT) {
            buf ^= 1;
            __syncthreads();
#pragma unroll
            for (int m = 0; m < 4; ++m) {
                Xs[buf][lk + m][ln] = (&ax.x)[m];   Xs[buf][lk + 4 + m][ln] = (&ay.x)[m];
                Ws2[buf][lk + m][ln] = (&bx.x)[m];  Ws2[buf][lk + 4 + m][ln] = (&by.x)[m];
            }
            __syncthreads();
        }
    }
    float4 bb0 = *(const float4*)(bias + m0 + tx);
    float4 bb1 = *(const float4*)(bias + m0 + tx + 4);
#pragma unroll
    for (int i = 0; i < 8; ++i) {
        float* cp = g_xp + (size_t)(n0 + ty + i) * R4H + m0 + tx;
        float4 o0, o1;
#pragma unroll
        for (int j = 0; j < 4; ++j) { (&o0.x)[j] = acc[i][j] + (&bb0.x)[j];
                                      (&o1.x)[j] = acc[i][4 + j] + (&bb1.x)[j]; }
        *(float4*)cp = o0; *(float4*)(cp + 4) = o1;
    }
}

// ---------------------------------------------------------------- LSTM
__global__ void __launch_bounds__(NTH, 1)
lstm_kernel(const float* __restrict__ c0, const float* __restrict__ W_hh,
            const float* __restrict__ b_hh, float* __restrict__ out) {
    extern __shared__ __align__(16) unsigned char smem_raw[];
    __half* Ws = reinterpret_cast<__half*>(smem_raw);
    float* pre_part = reinterpret_cast<float*>(smem_raw + (size_t)ROWS * HV * 2);

    const int tid = threadIdx.x, cta = blockIdx.x;
    const int j0 = cta * JPC;
    int J = HV - j0; if (J > JPC) J = JPC; if (J < 0) J = 0;

    // stage W_hh slice -> SMEM fp16. row rl = jl*4+gate <- W_hh[gate*HV + j0+jl]
    for (int e = tid; e < ROWS * HV; e += NTH) {
        int rl = e >> 11, k = e & (HV - 1);
        int jl = rl >> 2, gate = rl & 3;
        float w = (jl < J) ? W_hh[((size_t)gate * HV + (size_t)(j0 + jl)) * HV + k] : 0.f;
        Ws[e] = __float2half(w);
    }

    const int warp = tid >> 5, lane = tid & 31;
    const int grp = warp >> 1, hf = warp & 1;
    const int kb = hf << 10;
    const int rbase = grp * JPC;

    float c_val = 0.f, b_r[4];
#pragma unroll
    for (int g = 0; g < 4; ++g) b_r[g] = 0.f;
    if (tid < J) {
        c_val = c0[j0 + tid];
#pragma unroll
        for (int g = 0; g < 4; ++g) b_r[g] = b_hh[g * HV + j0 + tid];
    }
    __syncthreads();

    const uint4* Wq = reinterpret_cast<const uint4*>(Ws);
    const size_t wbase = (size_t)rbase * 256 + (size_t)hf * 128 + lane;
    volatile unsigned int* barp = &g_bar;

    // prefetch xp for t=0
    float xp_r[4] = {0.f, 0.f, 0.f, 0.f};
    if (tid < J) {
#pragma unroll
        for (int g = 0; g < 4; ++g)
            xp_r[g] = __ldcg(&g_xp[(size_t)0 * R4H + g * HV + j0 + tid]);
    }

    for (int t = 0; t < STEPS; ++t) {
        const int p = t & 1;

        // ---- h -> registers (L2-coherent loads)
        float hreg[32];
        {
            const float* hb = &g_h[p][kb + (lane << 3)];
#pragma unroll
            for (int it = 0; it < 4; ++it) {
                float4 v0 = __ldcg((const float4*)(hb + it * 256));
                float4 v1 = __ldcg((const float4*)(hb + it * 256 + 4));
#pragma unroll
                for (int m = 0; m < 4; ++m) {
                    hreg[it * 8 + m] = (&v0.x)[m];
                    hreg[it * 8 + 4 + m] = (&v1.x)[m];
                }
            }
        }

        float acc[JPC];
#pragma unroll
        for (int r = 0; r < JPC; ++r) acc[r] = 0.f;
#pragma unroll
        for (int it = 0; it < 4; ++it) {
#pragma unroll
            for (int r = 0; r < JPC; ++r) {
                uint4 w = Wq[wbase + (size_t)r * 256 + it * 32];
                float a = acc[r];
                float2 f;
                f = __half22float2(*(const __half2*)&w.x);
                a = fmaf(f.x, hreg[it * 8 + 0], a); a = fmaf(f.y, hreg[it * 8 + 1], a);
                f = __half22float2(*(const __half2*)&w.y);
                a = fmaf(f.x, hreg[it * 8 + 2], a); a = fmaf(f.y, hreg[it * 8 + 3], a);
                f = __half22float2(*(const __half2*)&w.z);
                a = fmaf(f.x, hreg[it * 8 + 4], a); a = fmaf(f.y, hreg[it * 8 + 5], a);
                f = __half22float2(*(const __half2*)&w.w);
                a = fmaf(f.x, hreg[it * 8 + 6], a); a = fmaf(f.y, hreg[it * 8 + 7], a);
                acc[r] = a;
            }
        }
#pragma unroll
        for (int r = 0; r < JPC; ++r) {
            float v = acc[r];
            v += __shfl_xor_sync(~0u, v, 16);
            v += __shfl_xor_sync(~0u, v, 8);
            v += __shfl_xor_sync(~0u, v, 4);
            v += __shfl_xor_sync(~0u, v, 2);
            v += __shfl_xor_sync(~0u, v, 1);
            if (lane == 0) pre_part[hf * ROWS + rbase + r] = v;
        }
        __syncthreads();

        if (tid < J) {
            const int rl = tid << 2;
            float pi = xp_r[0] + b_r[0] + pre_part[rl + 0] + pre_part[ROWS + rl + 0];
            float pf = xp_r[1] + b_r[1] + pre_part[rl + 1] + pre_part[ROWS + rl + 1];
            float po = xp_r[2] + b_r[2] + pre_part[rl + 2] + pre_part[ROWS + rl + 2];
            float pg = xp_r[3] + b_r[3] + pre_part[rl + 3] + pre_part[ROWS + rl + 3];
            float i_t = 1.0f / (1.0f + expf(-pi));
            float f_t = 1.0f / (1.0f + expf(-pf));
            float o_t = 1.0f / (1.0f + expf(-po));
            float g_t = tanhf(pg);
            c_val = c_val * f_t + i_t * g_t;
            float h_n = o_t * tanhf(c_val);
            g_h[p ^ 1][j0 + tid] = h_n;
            size_t oi = (size_t)t * HV + j0 + tid;
            out[oi] = h_n;
            out[OUTSTRIDE + oi] = f_t;
            out[2 * OUTSTRIDE + oi] = i_t;
        }

        // ---- grid barrier: REDG arrive, volatile-load spin
        __syncthreads();            // all g_h / out writes issued
        if (tid == 0) {
            __threadfence();        // publish g_h stores before arrive
            atomicAdd(&g_bar, 1u);  // result unused -> REDG
        }
        // prefetch xp for t+1 while other CTAs arrive
        if (t + 1 < STEPS && tid < J) {
#pragma unroll
            for (int g = 0; g < 4; ++g)
                xp_r[g] = __ldcg(&g_xp[(size_t)(t + 1) * R4H + g * HV + j0 + tid]);
        }
        if (tid == 0) {
            const unsigned tgt = (unsigned)(t + 1) * GRID;
            while (*barp < tgt) {}  // plain L2 load spin, no atomic RMW
            __threadfence();        // acquire before reading peers' g_h
        }
        __syncthreads();
    }
}

extern "C" void kernel_launch(void* const* d_in, const int* in_sizes, int n_in,
                              void* d_out, int out_size) {
    const float* input_ = (const float*)d_in[0];
    const float* h0 = (const float*)d_in[1];
    const float* c0 = (const float*)d_in[2];
    const float* W_ih = (const float*)d_in[3];
    const float* b_ih = (const float*)d_in[4];
    const float* W_hh = (const float*)d_in[5];
    const float* b_hh = (const float*)d_in[6];
    float* out = (float*)d_out;

    static int smem_set = 0;
    if (!smem_set) {
        cudaFuncSetAttribute(lstm_kernel, cudaFuncAttributeMaxDynamicSharedMemorySize,
                             LSTM_SMEM);
        smem_set = 1;
    }

    init_kernel<<<16, 128>>>(h0);
    gemm_xp<<<dim3(R4H / 128, STEPS / 128), 256>>>(input_, W_ih, b_ih);
    lstm_kernel<<<GRID, NTH, LSTM_SMEM>>>(c0, W_hh, b_hh, out);
}